// round 4
// baseline (speedup 1.0000x reference)
#include <cuda_runtime.h>
#include <cstdint>

// Upscaler W=8, R=4: out[b, 4*i+r, h] = (0.25r)*Z[b,i,h] + (1-0.25r)*Z[b,i-1,h]
// Row-norm denominator == 1.0f exactly in fp32 for i>=1; i==0 normalized by (wa+eps).
// Chunked-persistent: 256 CTAs per batch, each walks 4 consecutive i0-pairs,
// carrying Z[i0+1] -> next pair's Z[i0-1] (2 row-loads per pair instead of 3).

static constexpr int B_ = 4;
static constexpr int N_ = 2048;
static constexpr int H_ = 1024;
static constexpr int S_ = 8192;
static constexpr int H4 = H_ / 4;     // 256 float4 lanes per row
static constexpr int PAIRS = 4;       // i0-pairs per CTA
static constexpr int CTAS_X = (N_ / 2) / PAIRS;   // 256

__device__ __forceinline__ float4 blend(float wa, float wb, float4 a, float4 c) {
    float4 r;
    r.x = fmaf(wa, a.x, wb * c.x);
    r.y = fmaf(wa, a.y, wb * c.y);
    r.z = fmaf(wa, a.z, wb * c.z);
    r.w = fmaf(wa, a.w, wb * c.w);
    return r;
}

__global__ __launch_bounds__(H4, 8)
void Upscaler_33294586479031_kernel(const float4* __restrict__ Z,
                                    float4* __restrict__ out)
{
    const int b  = blockIdx.y;
    const int h  = threadIdx.x;
    int i0 = blockIdx.x * (2 * PAIRS);          // first block index of this chunk

    const float4* zb = Z   + (size_t)b * N_ * H4 + h;
    float4*       ob = out + (size_t)b * S_ * H4 + h;

    // zm = Z[b, i0-1, h] (undefined for i0==0, handled below)
    float4 zm;
    if (i0 > 0) zm = zb[(size_t)(i0 - 1) * H4];

    #pragma unroll
    for (int j = 0; j < PAIRS; ++j, i0 += 2) {
        // Two fresh, independent row loads per pair.
        const float4 z0 = zb[(size_t)i0 * H4];
        const float4 z1 = zb[(size_t)(i0 + 1) * H4];

        float4* o = ob + (size_t)(4 * i0) * H4;

        // Rows 4..7: blocks (i0, i0+1) — never the edge case.
        #pragma unroll
        for (int r = 0; r < 4; ++r) {
            const float wa = 0.25f * (float)r;
            __stcs(&o[(size_t)(r + 4) * H4], blend(wa, 1.0f - wa, z1, z0));
        }

        // Rows 0..3: blocks (i0-1, i0).
        if (i0 == 0) {
            #pragma unroll
            for (int r = 0; r < 4; ++r) {
                const float wa = 0.25f * (float)r;
                const float s  = wa / (wa + 1e-8f);     // 0 when r==0
                float4 res;
                res.x = z0.x * s; res.y = z0.y * s; res.z = z0.z * s; res.w = z0.w * s;
                __stcs(&o[(size_t)r * H4], res);
            }
        } else {
            #pragma unroll
            for (int r = 0; r < 4; ++r) {
                const float wa = 0.25f * (float)r;
                __stcs(&o[(size_t)r * H4], blend(wa, 1.0f - wa, z0, zm));
            }
        }

        zm = z1;   // carry forward: Z[i0+1] is next pair's Z[i0-1]
    }
}

extern "C" void kernel_launch(void* const* d_in, const int* in_sizes, int n_in,
                              void* d_out, int out_size)
{
    const float4* Z = (const float4*)d_in[0];
    float4* out = (float4*)d_out;

    dim3 grid(CTAS_X, B_);
    dim3 block(H4);
    Upscaler_33294586479031_kernel<<<grid, block>>>(Z, out);
}

// round 7
// speedup vs baseline: 1.0697x; 1.0697x over previous
#include <cuda_runtime.h>
#include <cstdint>

// Upscaler W=8, R=4: out[b, 4*i+r, h] = (0.25r)*Z[b,i,h] + (1-0.25r)*Z[b,i-1,h]
// Row-norm denominator == 1.0f exactly in fp32 for i>=1; i==0 normalized by (wa+eps).
// Shape: 4096 CTAs (one per (i0-pair, b)), 128 threads, 32B per thread per row.
// All global traffic uses 256-bit ops (the only width ptxas accepts L2 eviction
// hints on for sm_103a): Z loads evict_last (L2-resident across graph replays),
// out stores evict_first (pure streaming, don't evict Z).

static constexpr int B_ = 4;
static constexpr int N_ = 2048;
static constexpr int H_ = 1024;
static constexpr int S_ = 8192;
static constexpr int H4 = H_ / 4;   // 256 float4 per row
static constexpr int H8 = H_ / 8;   // 128 threads, 8 floats each

struct f8 { float4 a, b; };

__device__ __forceinline__ f8 ldg_keep8(const float4* p) {
    f8 v;
    asm volatile("ld.global.nc.L2::evict_last.v8.b32 "
                 "{%0,%1,%2,%3,%4,%5,%6,%7}, [%8];"
                 : "=f"(v.a.x), "=f"(v.a.y), "=f"(v.a.z), "=f"(v.a.w),
                   "=f"(v.b.x), "=f"(v.b.y), "=f"(v.b.z), "=f"(v.b.w)
                 : "l"(p));
    return v;
}

__device__ __forceinline__ void stg_stream8(float4* p, float4 a, float4 b) {
    asm volatile("st.global.L2::evict_first.v8.b32 "
                 "[%0], {%1,%2,%3,%4,%5,%6,%7,%8};"
                 :: "l"(p), "f"(a.x), "f"(a.y), "f"(a.z), "f"(a.w),
                    "f"(b.x), "f"(b.y), "f"(b.z), "f"(b.w)
                 : "memory");
}

__device__ __forceinline__ float4 blend(float wa, float wb, float4 a, float4 c) {
    float4 r;
    r.x = fmaf(wa, a.x, wb * c.x);
    r.y = fmaf(wa, a.y, wb * c.y);
    r.z = fmaf(wa, a.z, wb * c.z);
    r.w = fmaf(wa, a.w, wb * c.w);
    return r;
}

__device__ __forceinline__ float4 scale4(float4 a, float s) {
    float4 r; r.x = a.x * s; r.y = a.y * s; r.z = a.z * s; r.w = a.w * s;
    return r;
}

__global__ __launch_bounds__(H8, 8)
void Upscaler_33294586479031_kernel(const float4* __restrict__ Z,
                                    float4* __restrict__ out)
{
    const int i0 = blockIdx.x * 2;      // even block index, 0..N-2
    const int b  = blockIdx.y;          // 0..B-1
    const int h  = threadIdx.x * 2;     // float4 index, even → 32B aligned

    const float4* zp = Z + ((size_t)b * N_ + i0) * H4 + h;

    // Front-batched independent 256-bit loads (MLP = 3), L2-resident policy.
    const f8 z0 = ldg_keep8(zp);
    const f8 z1 = ldg_keep8(zp + H4);
    f8 zm;
    if (i0 > 0) zm = ldg_keep8(zp - H4);

    float4* o = out + ((size_t)b * S_ + 4 * (size_t)i0) * H4 + h;

    // Rows 4..7: blocks (i0, i0+1) — never the edge case.
    #pragma unroll
    for (int r = 0; r < 4; ++r) {
        const float wa = 0.25f * (float)r;
        const float wb = 1.0f - wa;
        stg_stream8(&o[(size_t)(r + 4) * H4],
                    blend(wa, wb, z1.a, z0.a), blend(wa, wb, z1.b, z0.b));
    }

    // Rows 0..3: blocks (i0-1, i0).
    if (i0 > 0) {
        #pragma unroll
        for (int r = 0; r < 4; ++r) {
            const float wa = 0.25f * (float)r;
            const float wb = 1.0f - wa;
            stg_stream8(&o[(size_t)r * H4],
                        blend(wa, wb, z0.a, zm.a), blend(wa, wb, z0.b, zm.b));
        }
    } else {
        #pragma unroll
        for (int r = 0; r < 4; ++r) {
            const float wa = 0.25f * (float)r;
            const float s  = wa / (wa + 1e-8f);     // 0 when r==0
            stg_stream8(&o[(size_t)r * H4], scale4(z0.a, s), scale4(z0.b, s));
        }
    }
}

extern "C" void kernel_launch(void* const* d_in, const int* in_sizes, int n_in,
                              void* d_out, int out_size)
{
    const float4* Z = (const float4*)d_in[0];
    float4* out = (float4*)d_out;

    dim3 grid(N_ / 2, B_);
    dim3 block(H8);
    Upscaler_33294586479031_kernel<<<grid, block>>>(Z, out);
}